// round 17
// baseline (speedup 1.0000x reference)
#include <cuda_runtime.h>

#define NP      3072
#define SPLITS  37
#define CHUNK   84              // 37*84 = 3108 >= 3072 (padded)
#define HC      (CHUNK / 2)     // 42 packed iterations
#define TPB     128
#define JBLK    (NP / TPB)      // 24 -> grid = 24*37 = 888 = 6*148 blocks (1 wave, occ 6)

#define RJ      32              // j per reduce block
#define RBLK    (NP / RJ)       // 96 reduce blocks
#define NSL     4               // split-slices per (c,j)
#define TPB2    (RJ * 6 * NSL)  // 768 threads

// constants (sigma = 1, A = 1/sqrt(2), A^2 = 1/2)
#define A_CONST 0.7071067811865476f
#define C1      0.7978845608028654f     // 2A/sqrt(pi) == 4A^3/sqrt(pi) since A^2=1/2
#define NC      14.399645f              // 90.4756 / (2*pi)
// Abramowitz-Stegun 7.1.26 erfc: erfc(x) = g*t*P(t), t=1/(1+p*x), |err|<=1.5e-7
#define P_AS  0.3275911f
#define PA    (P_AS * A_CONST)
#define AS1   0.254829592f
#define AS2  -0.284496736f
#define AS3   1.421413741f
#define AS4  -1.453152027f
#define AS5   1.061405429f
#define NL2E_HALF (-0.7213475204444817f)  // -0.5*log2(e)
#define RCUT2     20.25f                   // beyond this erf=1,g=0 to ~1e-4 rel
#define INFF      (__int_as_float(0x7f800000))

typedef unsigned long long u64;

__device__ float g_part[SPLITS * 6 * NP];
__device__ float g_potblk[RBLK];
__device__ int   g_sem;          // reset in-kernel after use

__device__ __forceinline__ float rcp_fast(float x) {
    float y; asm("rcp.approx.f32 %0, %1;" : "=f"(y) : "f"(x)); return y;
}
__device__ __forceinline__ float ex2_fast(float x) {
    float y; asm("ex2.approx.f32 %0, %1;" : "=f"(y) : "f"(x)); return y;
}
__device__ __forceinline__ u64 pk(float lo, float hi) {
    u64 r; asm("mov.b64 %0, {%1, %2};" : "=l"(r) : "f"(lo), "f"(hi)); return r;
}
__device__ __forceinline__ void upk(u64 a, float& lo, float& hi) {
    asm("mov.b64 {%0, %1}, %2;" : "=f"(lo), "=f"(hi) : "l"(a));
}
__device__ __forceinline__ u64 fma2(u64 a, u64 b, u64 c) {
    u64 d; asm("fma.rn.f32x2 %0, %1, %2, %3;" : "=l"(d) : "l"(a), "l"(b), "l"(c)); return d;
}
__device__ __forceinline__ u64 mul2(u64 a, u64 b) {
    u64 d; asm("mul.rn.f32x2 %0, %1, %2;" : "=l"(d) : "l"(a), "l"(b)); return d;
}
__device__ __forceinline__ u64 add2(u64 a, u64 b) {
    u64 d; asm("add.rn.f32x2 %0, %1, %2;" : "=l"(d) : "l"(a), "l"(b)); return d;
}

// scalar correction for one near pair: adds (true - bare) deltas.
// Updates A1, A2, M (= H - G), W.   (u passed POSITIVE here)
__device__ __forceinline__ void corr_half(
    float dx, float dy, float dz, float qi,
    float ux, float uy, float uz, bool act,
    float& A1, float& A2,
    float& Mx, float& My, float& Mz,
    float& Wx, float& Wy, float& Wz)
{
    float t0 = dx * dx;
    t0 = fmaf(dy, dy, t0);
    const float d2 = fmaf(dz, dz, t0);
    const bool on = act && (d2 != 0.f) && (d2 < RCUT2);
    const float d2s  = fmaxf(d2, 1e-8f);
    const float rinv = rsqrtf(d2s);
    const float m    = on ? 1.f : 0.f;
    const float g    = ex2_fast(NL2E_HALF * d2s) * m;
    const float rn   = d2s * rinv;
    const float tt   = rcp_fast(fmaf(PA, rn, 1.f));
    const float poly = fmaf(fmaf(fmaf(fmaf(AS5, tt, AS4), tt, AS3), tt, AS2), tt, AS1);
    const float erfc = g * tt * poly;
    const float de   = -erfc * rinv;
    const float rr   = rinv * rinv;
    const float c1g  = C1 * g;
    const float ds1  = (de - c1g) * rr;
    const float uri  = fmaf(ux, dx, fmaf(uy, dy, uz * dz));
    const float ds2r = fmaf(3.f, ds1, -c1g) * (uri * rr);
    A1 = fmaf(qi, de, A1);
    A2 = fmaf(ds1, uri, A2);
    Mx = fmaf(ds2r, dx, Mx); Mx = fmaf(-ds1, ux, Mx);
    My = fmaf(ds2r, dy, My); My = fmaf(-ds1, uy, My);
    Mz = fmaf(ds2r, dz, Mz); Mz = fmaf(-ds1, uz, Mz);
    const float qd = qi * ds1;
    Wx = fmaf(qd, dx, Wx); Wy = fmaf(qd, dy, Wy); Wz = fmaf(qd, dz, Wz);
}

__global__ __launch_bounds__(TPB, 6)
void ewald_pair_kernel(const float* __restrict__ q,
                       const float* __restrict__ r,
                       const float* __restrict__ u)
{
    const int j  = blockIdx.x * TPB + threadIdx.x;
    const int s  = blockIdx.y;
    const int i0 = s * CHUNK;

    __shared__ ulonglong2 s_p0[HC];   // {-rx2, -ry2}
    __shared__ ulonglong2 s_p1[HC];   // {-rz2,   q2}
    __shared__ ulonglong2 s_p2[HC];   // {-ux2, -uy2}   (u stored NEGATED)
    __shared__ u64        s_p3[HC];   // {-uz2}

    for (int t = threadIdx.x; t < HC; t += TPB) {
        const int ia = i0 + t;
        const int ib = ia + HC;
        float rxa, rya, rza, qa, uxa, uya, uza;
        float rxb, ryb, rzb, qb, uxb, uyb, uzb;
        if (ia < NP) {
            rxa = r[3*ia+0]; rya = r[3*ia+1]; rza = r[3*ia+2];
            qa = q[ia]; uxa = u[3*ia+0]; uya = u[3*ia+1]; uza = u[3*ia+2];
        } else { rxa=1e4f; rya=1e4f; rza=1e4f; qa=0.f; uxa=0.f; uya=0.f; uza=0.f; }
        if (ib < NP) {
            rxb = r[3*ib+0]; ryb = r[3*ib+1]; rzb = r[3*ib+2];
            qb = q[ib]; uxb = u[3*ib+0]; uyb = u[3*ib+1]; uzb = u[3*ib+2];
        } else { rxb=1e4f; ryb=1e4f; rzb=1e4f; qb=0.f; uxb=0.f; uyb=0.f; uzb=0.f; }
        s_p0[t] = make_ulonglong2(pk(-rxa, -rxb), pk(-rya, -ryb));
        s_p1[t] = make_ulonglong2(pk(-rza, -rzb), pk(qa, qb));
        s_p2[t] = make_ulonglong2(pk(-uxa, -uxb), pk(-uya, -uyb));
        s_p3[t] = pk(-uza, -uzb);
    }
    __syncthreads();

    const float rjx = r[3*j+0], rjy = r[3*j+1], rjz = r[3*j+2];
    const float ujx = u[3*j+0], ujy = u[3*j+1], ujz = u[3*j+2];

    const u64 rjx2 = pk(rjx, rjx), rjy2 = pk(rjy, rjy), rjz2 = pk(rjz, rjz);
    const u64 kNegThree = 0xC0400000C0400000ull;   // packed {-3, -3}

    u64 a1 = 0, a2n = 0;                 // a2n accumulates -Sum s1*uri
    u64 mx = 0, my = 0, mz = 0;          // accumulates M = H - G directly
    u64 wx = 0, wy = 0, wz = 0;          // Sum q*s1*d
    u64 mask = 0;

    // ---------------- Pass A: bare Coulomb (erf=1, g=0) for ALL pairs ----------------
    // unroll 14 (42 = 3*14): lets ptxas software-pipeline the LDS + scalar MUFU
    // section across iterations instead of serializing on each rsqrt chain.
#pragma unroll 14
    for (int t = 0; t < HC; ++t) {
        const ulonglong2 p0 = s_p0[t];
        const ulonglong2 p1 = s_p1[t];
        const ulonglong2 p2 = s_p2[t];
        const u64 nuz2 = s_p3[t];

        const u64 dx = add2(rjx2, p0.x);
        const u64 dy = add2(rjy2, p0.y);
        const u64 dz = add2(rjz2, p1.x);
        u64 d2 = mul2(dx, dx);
        d2 = fma2(dy, dy, d2);
        d2 = fma2(dz, dz, d2);

        // self-mask BEFORE rsqrt: d2==0 -> +inf, rsqrt(+inf)=+0 natively
        float d2l, d2h; upk(d2, d2l, d2h);
        d2l = (d2l == 0.f) ? INFF : d2l;
        d2h = (d2h == 0.f) ? INFF : d2h;
        // near test on patched d2 (self auto-excluded since d2=inf)
        const bool near = fminf(d2l, d2h) < RCUT2;
        mask |= ((u64)near) << t;

        const float rl = rsqrtf(d2l);
        const float rh = rsqrtf(d2h);
        const u64 rinv = pk(rl, rh);
        const u64 rr   = mul2(rinv, rinv);
        const u64 s1   = mul2(rinv, rr);

        a1 = fma2(p1.y, rinv, a1);

        // urin = (-u) . d = -uri
        u64 urin = mul2(p2.x, dx);
        urin = fma2(p2.y, dy, urin);
        urin = fma2(nuz2, dz, urin);
        a2n = fma2(s1, urin, a2n);             // = -Sum s1*uri

        const u64 v   = mul2(urin, rr);        // -uri*rr
        const u64 sv  = mul2(s1, v);           // -s1*uri*rr
        const u64 s2r = mul2(sv, kNegThree);   // +3*s1*uri*rr = s2r (positive)

        // M += s2r*d + s1*(-u) = s2r*d - s1*u  (= H - G)
        mx = fma2(s2r, dx, mx); mx = fma2(s1, p2.x, mx);
        my = fma2(s2r, dy, my); my = fma2(s1, p2.y, my);
        mz = fma2(s2r, dz, mz); mz = fma2(s1, nuz2, mz);

        const u64 qs1 = mul2(p1.y, s1);
        wx = fma2(qs1, dx, wx);
        wy = fma2(qs1, dy, wy);
        wz = fma2(qs1, dz, wz);
    }

    float l, h;
    upk(a1, l, h);  float A1 = l + h;
    upk(a2n, l, h); float A2 = -(l + h);
    upk(mx, l, h);  float Mx = l + h;
    upk(my, l, h);  float My = l + h;
    upk(mz, l, h);  float Mz = l + h;
    upk(wx, l, h);  float Wx = l + h;
    upk(wy, l, h);  float Wy = l + h;
    upk(wz, l, h);  float Wz = l + h;

    // ---------------- Pass B: sparse erf/gauss corrections for near pairs ----------------
    unsigned mlo = (unsigned)mask;
    unsigned mhi = (unsigned)(mask >> 32);
    while (__any_sync(0xFFFFFFFFu, mlo | mhi)) {
        const bool act = (mlo | mhi) != 0u;
        int t = 0;
        if (mlo) { t = __ffs(mlo) - 1;  mlo &= mlo - 1u; }
        else if (mhi) { t = __ffs(mhi) + 31; mhi &= mhi - 1u; }

        const ulonglong2 p0 = s_p0[t];
        const ulonglong2 p1 = s_p1[t];
        const ulonglong2 p2 = s_p2[t];
        const u64 nuz2 = s_p3[t];
        float nrxl, nrxh, nryl, nryh, nrzl, nrzh, ql, qh;
        float nuxl, nuxh, nuyl, nuyh, nuzl, nuzh;
        upk(p0.x, nrxl, nrxh); upk(p0.y, nryl, nryh);
        upk(p1.x, nrzl, nrzh); upk(p1.y, ql, qh);
        upk(p2.x, nuxl, nuxh); upk(p2.y, nuyl, nuyh);
        upk(nuz2, nuzl, nuzh);

        corr_half(rjx + nrxl, rjy + nryl, rjz + nrzl, ql, -nuxl, -nuyl, -nuzl, act,
                  A1, A2, Mx, My, Mz, Wx, Wy, Wz);
        corr_half(rjx + nrxh, rjy + nryh, rjz + nrzh, qh, -nuxh, -nuyh, -nuzh, act,
                  A1, A2, Mx, My, Mz, Wx, Wy, Wz);
    }

    const float fx = Wx + Mx, fy = Wy + My, fz = Wz + Mz;
    const float dd = ujx * Mx + ujy * My + ujz * Mz;

    float* p = g_part + (size_t)s * 6 * NP;
    p[0*NP + j] = A1;
    p[1*NP + j] = A2;
    p[2*NP + j] = fx;
    p[3*NP + j] = fy;
    p[4*NP + j] = fz;
    p[5*NP + j] = dd;
}

// 96 blocks x 768 threads, PDL: prologue + input prefetch overlap the pair kernel.
__global__ __launch_bounds__(TPB2)
void ewald_reduce_kernel(const float* __restrict__ q,
                         const float* __restrict__ kappa,
                         const float* __restrict__ alpha,
                         float* __restrict__ out)
{
    const int jl = threadIdx.x & 31;
    const int c  = (threadIdx.x >> 5) % 6;
    const int sl = threadIdx.x / 192;          // 0..3
    const int j  = blockIdx.x * RJ + jl;

    // prefetch pair-independent inputs BEFORE waiting on the pair kernel
    float ka = 0.f, al = 0.f, qj = 0.f;
    if (threadIdx.x < 32) {
        ka = kappa[j]; al = alpha[j]; qj = q[j];
    }

    asm volatile("griddepcontrol.wait;" ::: "memory");

    const float* base = g_part + (size_t)c * NP + j;
    float acc = 0.f;
#pragma unroll
    for (int k = 0; k < 9; ++k)                // 9 unpredicated loads: s = sl + 4k
        acc += base[(size_t)(sl + NSL * k) * 6 * NP];
    if (sl == 0)
        acc += base[(size_t)36 * 6 * NP];

    __shared__ float sh[NSL][6][RJ];
    sh[sl][c][jl] = acc;
    __syncthreads();

    if (threadIdx.x < 192) {   // slice 0: 6 warps combine the 4 slices
        sh[0][c][jl] = sh[0][c][jl] + sh[1][c][jl] + sh[2][c][jl] + sh[3][c][jl];
    }
    __syncthreads();

    float potj = 0.f;
    if (threadIdx.x < 32) {    // warp 0 does the per-j epilogue
        const float a1 = sh[0][0][jl], a2 = sh[0][1][jl];
        const float fx = sh[0][2][jl], fy = sh[0][3][jl], fz = sh[0][4][jl], dd = sh[0][5][jl];

        const float ephi = NC * (a1 + a2);
        const float qind = -ka * ephi;
        const float efx = NC * fx, efy = NC * fy, efz = NC * fz;

        out[1 + j] = qind;
        out[1 + NP + 3*j + 0] = al * efx;
        out[1 + NP + 3*j + 1] = al * efy;
        out[1 + NP + 3*j + 2] = al * efz;

        potj = qj * NC * (0.5f * a1 + a2)
             - 0.5f * NC * dd
             - 0.5f * ka * ephi * ephi
             - 0.5f * al * (efx * efx + efy * efy + efz * efz);

#pragma unroll
        for (int ofs = 16; ofs > 0; ofs >>= 1)
            potj += __shfl_down_sync(0xFFFFFFFFu, potj, ofs);
    }

    __shared__ bool lastblk;
    if (threadIdx.x == 0) {
        g_potblk[blockIdx.x] = potj;
        __threadfence();
        const int old = atomicAdd(&g_sem, 1);
        lastblk = (old == RBLK - 1);
    }
    __syncthreads();

    if (lastblk && threadIdx.x < 32) {
        __threadfence();
        const int t = threadIdx.x;
        float v = g_potblk[t] + g_potblk[t + 32] + g_potblk[t + 64];
#pragma unroll
        for (int ofs = 16; ofs > 0; ofs >>= 1)
            v += __shfl_down_sync(0xFFFFFFFFu, v, ofs);
        if (t == 0) {
            out[0] = v;
            g_sem = 0;    // reset for next graph replay
        }
    }
}

extern "C" void kernel_launch(void* const* d_in, const int* in_sizes, int n_in,
                              void* d_out, int out_size)
{
    const float* q     = (const float*)d_in[0];
    const float* r     = (const float*)d_in[1];
    const float* u     = (const float*)d_in[4];
    const float* kappa = (const float*)d_in[5];
    const float* alpha = (const float*)d_in[6];
    float* out = (float*)d_out;

    dim3 grid1(JBLK, SPLITS);
    ewald_pair_kernel<<<grid1, TPB>>>(q, r, u);

    cudaLaunchConfig_t cfg = {};
    cfg.gridDim  = dim3(RBLK, 1, 1);
    cfg.blockDim = dim3(TPB2, 1, 1);
    cfg.dynamicSmemBytes = 0;
    cudaLaunchAttribute attrs[1];
    attrs[0].id = cudaLaunchAttributeProgrammaticStreamSerialization;
    attrs[0].val.programmaticStreamSerializationAllowed = 1;
    cfg.attrs = attrs;
    cfg.numAttrs = 1;

    cudaError_t e = cudaLaunchKernelEx(&cfg, ewald_reduce_kernel, q, kappa, alpha, out);
    if (e != cudaSuccess) {
        ewald_reduce_kernel<<<RBLK, TPB2>>>(q, kappa, alpha, out);
    }
}